// round 1
// baseline (speedup 1.0000x reference)
#include <cuda_runtime.h>

// Problem constants: B=4, S=1024, D=512, H=8, DH=64
#define RQ   4096            // B*S rows per tensor
#define R3   12288           // 3 tensors stacked
#define DD   512
#define NH   8
#define DH   64
#define NPAIR 32             // H*B head-batch pairs
#define LN_EPS 1e-5f

// ---------------- scratch (device globals; no allocation) ----------------
__device__ float g_f[3 * RQ * DD];        // f_q | f_k | f_v  (post LN+W_in)   24MB
__device__ float g_g[RQ * DD];            // attention output pre-W_out        8MB
__device__ float g_lnmu[R3];
__device__ float g_lnrs[R3];
__device__ float g_hmu[2 * NPAIR * 1024]; // head row stats for f_q(0), f_k(1)
__device__ float g_hinvn[2 * NPAIR * 1024];
__device__ float g_hvar[2 * NPAIR * 1024];
__device__ float g_Mpart[NPAIR * 8 * 2 * 4096]; // per (pair,split): M1,M2     8MB
__device__ float g_rpart[NPAIR * 8 * 64];
__device__ float g_M[NPAIR * 2 * 4096];
__device__ float g_r[NPAIR * 64];

// ---------------- 1) LayerNorm row statistics ----------------
__global__ void ln_stats(const float* __restrict__ q, const float* __restrict__ k,
                         const float* __restrict__ v)
{
    int gw   = (blockIdx.x * blockDim.x + threadIdx.x) >> 5;
    int lane = threadIdx.x & 31;
    if (gw >= R3) return;
    const float* src = (gw < RQ) ? q : (gw < 2 * RQ ? k : v);
    int row = gw & (RQ - 1);
    const float4* p = (const float4*)(src + (size_t)row * DD);
    float s = 0.f, ss = 0.f;
#pragma unroll
    for (int i = 0; i < 4; i++) {
        float4 x = p[lane + i * 32];
        s  += x.x + x.y + x.z + x.w;
        ss += x.x * x.x + x.y * x.y + x.z * x.z + x.w * x.w;
    }
#pragma unroll
    for (int o = 16; o; o >>= 1) {
        s  += __shfl_xor_sync(0xffffffffu, s, o);
        ss += __shfl_xor_sync(0xffffffffu, ss, o);
    }
    if (lane == 0) {
        float mu  = s * (1.f / 512.f);
        float var = ss * (1.f / 512.f) - mu * mu;
        g_lnmu[gw] = mu;
        g_lnrs[gw] = rsqrtf(var + LN_EPS);
    }
}

// ---------------- 2) fused LN + GEMM: g_f = LN(X) @ W_in ----------------
// 128x128 tile, BK=8, 256 threads, 8x8 per thread (split 4+4 halves)
__global__ void __launch_bounds__(256) gemm_ln(
    const float* __restrict__ q, const float* __restrict__ k,
    const float* __restrict__ v, const float* __restrict__ lng,
    const float* __restrict__ lnb, const float* __restrict__ W)
{
    __shared__ float As[8][132];
    __shared__ float Bs[8][128];
    int t = threadIdx.x;
    int n0 = blockIdx.x * 128;
    int rowbase = blockIdx.y * 128;
    const float* src = (rowbase < RQ) ? q : (rowbase < 2 * RQ ? k : v);
    int lrowbase = rowbase & (RQ - 1);

    int arow = t >> 1;
    int ac4  = (t & 1) * 4;
    float mu = g_lnmu[rowbase + arow];
    float rs = g_lnrs[rowbase + arow];
    const float* aptr = src + (size_t)(lrowbase + arow) * DD;

    int brow = t >> 5;
    int bc4  = (t & 31) * 4;

    int tx = t & 15, ty = t >> 4;
    float acc[2][2][4][4];
#pragma unroll
    for (int a = 0; a < 2; a++)
#pragma unroll
        for (int b = 0; b < 2; b++)
#pragma unroll
            for (int i = 0; i < 4; i++)
#pragma unroll
                for (int j = 0; j < 4; j++) acc[a][b][i][j] = 0.f;

    for (int k0 = 0; k0 < DD; k0 += 8) {
        float4 x  = *(const float4*)(aptr + k0 + ac4);
        float4 gg = *(const float4*)(lng + k0 + ac4);
        float4 bb = *(const float4*)(lnb + k0 + ac4);
        As[ac4 + 0][arow] = (x.x - mu) * rs * gg.x + bb.x;
        As[ac4 + 1][arow] = (x.y - mu) * rs * gg.y + bb.y;
        As[ac4 + 2][arow] = (x.z - mu) * rs * gg.z + bb.z;
        As[ac4 + 3][arow] = (x.w - mu) * rs * gg.w + bb.w;
        *(float4*)&Bs[brow][bc4] =
            *(const float4*)(W + (size_t)(k0 + brow) * DD + n0 + bc4);
        __syncthreads();
#pragma unroll
        for (int kk = 0; kk < 8; kk++) {
            float4 a0 = *(float4*)&As[kk][ty * 4];
            float4 a1 = *(float4*)&As[kk][64 + ty * 4];
            float4 b0 = *(float4*)&Bs[kk][tx * 4];
            float4 b1 = *(float4*)&Bs[kk][64 + tx * 4];
            float av[2][4] = {{a0.x, a0.y, a0.z, a0.w}, {a1.x, a1.y, a1.z, a1.w}};
            float bv[2][4] = {{b0.x, b0.y, b0.z, b0.w}, {b1.x, b1.y, b1.z, b1.w}};
#pragma unroll
            for (int rh = 0; rh < 2; rh++)
#pragma unroll
                for (int ch = 0; ch < 2; ch++)
#pragma unroll
                    for (int i = 0; i < 4; i++)
#pragma unroll
                        for (int j = 0; j < 4; j++)
                            acc[rh][ch][i][j] += av[rh][i] * bv[ch][j];
        }
        __syncthreads();
    }
#pragma unroll
    for (int rh = 0; rh < 2; rh++)
#pragma unroll
        for (int i = 0; i < 4; i++) {
            int row = rowbase + rh * 64 + ty * 4 + i;
#pragma unroll
            for (int ch = 0; ch < 2; ch++) {
                int col = n0 + ch * 64 + tx * 4;
                float4 o = {acc[rh][ch][i][0], acc[rh][ch][i][1],
                            acc[rh][ch][i][2], acc[rh][ch][i][3]};
                *(float4*)&g_f[(size_t)row * DD + col] = o;
            }
        }
}

// ---------------- 3) per-head row stats for f_q, f_k ----------------
__global__ void head_stats()
{
    int gw   = (blockIdx.x * blockDim.x + threadIdx.x) >> 5;
    int lane = threadIdx.x & 31;
    if (gw >= 2 * NPAIR * 1024) return;
    int which = gw >> 15;
    int rem   = gw & 32767;
    int hb    = rem >> 10;
    int m     = rem & 1023;
    int h = hb >> 2, b = hb & 3;
    const float* p = g_f + (size_t)which * RQ * DD + (size_t)(b * 1024 + m) * DD + h * DH;
    float x0 = p[lane], x1 = p[lane + 32];
    float s = x0 + x1, ss = x0 * x0 + x1 * x1;
#pragma unroll
    for (int o = 16; o; o >>= 1) {
        s  += __shfl_xor_sync(0xffffffffu, s, o);
        ss += __shfl_xor_sync(0xffffffffu, ss, o);
    }
    if (lane == 0) {
        g_hmu[gw]   = s * (1.f / 64.f);
        g_hinvn[gw] = rsqrtf(ss);                          // 1 / ||f||
        g_hvar[gw]  = (ss - s * s * (1.f / 64.f)) * (1.f / 63.f); // ddof=1
    }
}

// ---------------- 4) M1/M2/r partial accumulation (m-split x8) ----------------
__global__ void __launch_bounds__(256) macc()
{
    __shared__ float Ks[32][64];
    __shared__ float Vs[32][64];
    __shared__ float skm[32], sikn[32], skv[32];
    int t = threadIdx.x;
    int pair  = blockIdx.x >> 3;
    int split = blockIdx.x & 7;
    int h = pair >> 2, b = pair & 3;
    const float* fk = g_f + (size_t)RQ * DD     + (size_t)(b * 1024) * DD + h * DH;
    const float* fv = g_f + (size_t)2 * RQ * DD + (size_t)(b * 1024) * DD + h * DH;
    int tx = t & 15, ty = t >> 4;
    int d0 = ty * 4, e0 = tx * 4;
    float M1a[4][4] = {}, M2a[4][4] = {}, ra[4] = {};
    int mbase0 = split * 128;

    for (int c = 0; c < 4; c++) {
        int mbase = mbase0 + c * 32;
#pragma unroll
        for (int i = 0; i < 2; i++) {
            int fi = t + i * 256;
            int rr = fi >> 4;
            int c4 = (fi & 15) * 4;
            *(float4*)&Ks[rr][c4] = *(const float4*)(fk + (size_t)(mbase + rr) * DD + c4);
            *(float4*)&Vs[rr][c4] = *(const float4*)(fv + (size_t)(mbase + rr) * DD + c4);
        }
        if (t < 32) {
            int idx = 32768 + pair * 1024 + mbase + t;
            skm[t]  = g_hmu[idx];
            sikn[t] = g_hinvn[idx];
            skv[t]  = g_hvar[idx];
        }
        __syncthreads();
#pragma unroll 8
        for (int mm = 0; mm < 32; mm++) {
            float km = skm[mm], ikn = sikn[mm];
            float4 kk4 = *(float4*)&Ks[mm][d0];
            float4 vv4 = *(float4*)&Vs[mm][e0];
            float a1[4] = {kk4.x - km, kk4.y - km, kk4.z - km, kk4.w - km};
            float a2[4] = {kk4.x * ikn, kk4.y * ikn, kk4.z * ikn, kk4.w * ikn};
            float vv[4] = {vv4.x, vv4.y, vv4.z, vv4.w};
#pragma unroll
            for (int i = 0; i < 4; i++)
#pragma unroll
                for (int j = 0; j < 4; j++) {
                    M1a[i][j] += a1[i] * vv[j];
                    M2a[i][j] += a2[i] * vv[j];
                }
        }
        if (ty == 0) {
#pragma unroll 8
            for (int mm = 0; mm < 32; mm++) {
                float kvv = skv[mm];
#pragma unroll
                for (int j = 0; j < 4; j++) ra[j] += kvv * Vs[mm][e0 + j];
            }
        }
        __syncthreads();
    }
    float* mp = g_Mpart + (size_t)blockIdx.x * 8192;
#pragma unroll
    for (int i = 0; i < 4; i++)
#pragma unroll
        for (int j = 0; j < 4; j++) {
            mp[(d0 + i) * 64 + e0 + j]        = M1a[i][j];
            mp[4096 + (d0 + i) * 64 + e0 + j] = M2a[i][j];
        }
    if (ty == 0)
#pragma unroll
        for (int j = 0; j < 4; j++) g_rpart[blockIdx.x * 64 + e0 + j] = ra[j];
}

// ---------------- 5) reduce 8 partials per pair ----------------
__global__ void mreduce()
{
    int p = blockIdx.x, t = threadIdx.x;
    for (int idx = t; idx < 8192; idx += 256) {
        float s = 0.f;
#pragma unroll
        for (int sp = 0; sp < 8; sp++) s += g_Mpart[(size_t)(p * 8 + sp) * 8192 + idx];
        g_M[(size_t)p * 8192 + idx] = s;
    }
    if (t < 64) {
        float s = 0.f;
#pragma unroll
        for (int sp = 0; sp < 8; sp++) s += g_rpart[(p * 8 + sp) * 64 + t];
        g_r[p * 64 + t] = s;
    }
}

// ---------------- 6) apply: out_head[n] = a*q_c@M1 + b*q@M2 + g*r ----------------
__global__ void __launch_bounds__(256) apply_k(const float* __restrict__ cov_w,
                                               const float* __restrict__ var_w)
{
    __shared__ float Ms[2 * 4096];   // M1 | M2
    __shared__ float qs[64][34];     // [d][row], 32 rows per block, padded
    __shared__ float scs1[64], srs[64];
    __shared__ float sbeta[32], sgamma[32], smual[32];
    int t = threadIdx.x;
    int pair  = blockIdx.x >> 5;
    int ntile = blockIdx.x & 31;
    int h = pair >> 2, b = pair & 3;
    float cw = cov_w[0], vw = var_w[0];
    float w3 = 1.f - cw - vw;
    float alpha = cw * (1.f / 64.f);

    const float* msrc = g_M + (size_t)pair * 8192;
#pragma unroll
    for (int i = 0; i < 8; i++) {
        int fi = t + i * 256;
        ((float4*)Ms)[fi] = ((const float4*)msrc)[fi];
    }
    int n0 = ntile * 32;
    const float* fq = g_f + (size_t)(b * 1024 + n0) * DD + h * DH;
#pragma unroll
    for (int i = 0; i < 2; i++) {
        int fi = t + i * 256;
        int rr = fi >> 4, c4 = (fi & 15) * 4;
        float4 x = *(const float4*)(fq + (size_t)rr * DD + c4);
        qs[c4 + 0][rr] = x.x; qs[c4 + 1][rr] = x.y;
        qs[c4 + 2][rr] = x.z; qs[c4 + 3][rr] = x.w;
    }
    if (t < 32) {
        int idx = pair * 1024 + n0 + t;
        float mu = g_hmu[idx], invn = g_hinvn[idx], var = g_hvar[idx];
        sbeta[t]  = w3 * invn;
        sgamma[t] = vw * (1.f / 64.f) * var;
        smual[t]  = alpha * mu;
    }
    if (t < 64) srs[t] = g_r[pair * 64 + t];
    __syncthreads();
    if (t < 64) {
        float s = 0.f;
#pragma unroll
        for (int d = 0; d < 64; d++) s += Ms[d * 64 + t];
        scs1[t] = s;
    }
    __syncthreads();

    int tx = t & 15, ty = t >> 4;
    int e0 = tx * 4, r0 = ty * 2;
    float t1[2][4] = {}, t2[2][4] = {};
#pragma unroll 8
    for (int d = 0; d < 64; d++) {
        float4 m1 = *(float4*)&Ms[d * 64 + e0];
        float4 m2 = *(float4*)&Ms[4096 + d * 64 + e0];
        float q0 = qs[d][r0], q1 = qs[d][r0 + 1];
        t1[0][0] += q0 * m1.x; t1[0][1] += q0 * m1.y; t1[0][2] += q0 * m1.z; t1[0][3] += q0 * m1.w;
        t1[1][0] += q1 * m1.x; t1[1][1] += q1 * m1.y; t1[1][2] += q1 * m1.z; t1[1][3] += q1 * m1.w;
        t2[0][0] += q0 * m2.x; t2[0][1] += q0 * m2.y; t2[0][2] += q0 * m2.z; t2[0][3] += q0 * m2.w;
        t2[1][0] += q1 * m2.x; t2[1][1] += q1 * m2.y; t2[1][2] += q1 * m2.z; t2[1][3] += q1 * m2.w;
    }
#pragma unroll
    for (int i = 0; i < 2; i++) {
        int row = r0 + i;
        int n = n0 + row;
        float beta = sbeta[row], gamma = sgamma[row], mal = smual[row];
        float4 o;
        o.x = alpha * t1[i][0] - mal * scs1[e0 + 0] + beta * t2[i][0] + gamma * srs[e0 + 0];
        o.y = alpha * t1[i][1] - mal * scs1[e0 + 1] + beta * t2[i][1] + gamma * srs[e0 + 1];
        o.z = alpha * t1[i][2] - mal * scs1[e0 + 2] + beta * t2[i][2] + gamma * srs[e0 + 2];
        o.w = alpha * t1[i][3] - mal * scs1[e0 + 3] + beta * t2[i][3] + gamma * srs[e0 + 3];
        *(float4*)&g_g[(size_t)(b * 1024 + n) * DD + h * DH + e0] = o;
    }
}

// ---------------- 7) GEMM: out = g_g @ W_out + b_out ----------------
__global__ void __launch_bounds__(256) gemm_bias(const float* __restrict__ W,
                                                 const float* __restrict__ bias,
                                                 float* __restrict__ out)
{
    __shared__ float As[8][132];
    __shared__ float Bs[8][128];
    int t = threadIdx.x;
    int n0 = blockIdx.x * 128;
    int rowbase = blockIdx.y * 128;

    int arow = t >> 1;
    int ac4  = (t & 1) * 4;
    const float* aptr = g_g + (size_t)(rowbase + arow) * DD;
    int brow = t >> 5;
    int bc4  = (t & 31) * 4;
    int tx = t & 15, ty = t >> 4;
    float acc[2][2][4][4];
#pragma unroll
    for (int a = 0; a < 2; a++)
#pragma unroll
        for (int b = 0; b < 2; b++)
#pragma unroll
            for (int i = 0; i < 4; i++)
#pragma unroll
                for (int j = 0; j < 4; j++) acc[a][b][i][j] = 0.f;

    for (int k0 = 0; k0 < DD; k0 += 8) {
        float4 x = *(const float4*)(aptr + k0 + ac4);
        As[ac4 + 0][arow] = x.x;
        As[ac4 + 1][arow] = x.y;
        As[ac4 + 2][arow] = x.z;
        As[ac4 + 3][arow] = x.w;
        *(float4*)&Bs[brow][bc4] =
            *(const float4*)(W + (size_t)(k0 + brow) * DD + n0 + bc4);
        __syncthreads();
#pragma unroll
        for (int kk = 0; kk < 8; kk++) {
            float4 a0 = *(float4*)&As[kk][ty * 4];
            float4 a1 = *(float4*)&As[kk][64 + ty * 4];
            float4 b0 = *(float4*)&Bs[kk][tx * 4];
            float4 b1 = *(float4*)&Bs[kk][64 + tx * 4];
            float av[2][4] = {{a0.x, a0.y, a0.z, a0.w}, {a1.x, a1.y, a1.z, a1.w}};
            float bv[2][4] = {{b0.x, b0.y, b0.z, b0.w}, {b1.x, b1.y, b1.z, b1.w}};
#pragma unroll
            for (int rh = 0; rh < 2; rh++)
#pragma unroll
                for (int ch = 0; ch < 2; ch++)
#pragma unroll
                    for (int i = 0; i < 4; i++)
#pragma unroll
                        for (int j = 0; j < 4; j++)
                            acc[rh][ch][i][j] += av[rh][i] * bv[ch][j];
        }
        __syncthreads();
    }
#pragma unroll
    for (int rh = 0; rh < 2; rh++)
#pragma unroll
        for (int i = 0; i < 4; i++) {
            int row = rowbase + rh * 64 + ty * 4 + i;
#pragma unroll
            for (int ch = 0; ch < 2; ch++) {
                int col = n0 + ch * 64 + tx * 4;
                float4 bb = *(const float4*)(bias + col);
                float4 o = {acc[rh][ch][i][0] + bb.x, acc[rh][ch][i][1] + bb.y,
                            acc[rh][ch][i][2] + bb.z, acc[rh][ch][i][3] + bb.w};
                *(float4*)&out[(size_t)row * DD + col] = o;
            }
        }
}

// ---------------- launch ----------------
extern "C" void kernel_launch(void* const* d_in, const int* in_sizes, int n_in,
                              void* d_out, int out_size)
{
    const float* q     = (const float*)d_in[0];
    const float* k     = (const float*)d_in[1];
    const float* v     = (const float*)d_in[2];
    const float* ln_g  = (const float*)d_in[3];
    const float* ln_b  = (const float*)d_in[4];
    const float* W_in  = (const float*)d_in[5];
    const float* W_out = (const float*)d_in[6];
    const float* b_out = (const float*)d_in[7];
    const float* cov_w = (const float*)d_in[8];
    const float* var_w = (const float*)d_in[9];
    float* out = (float*)d_out;

    ln_stats<<<R3 / 8, 256>>>(q, k, v);
    gemm_ln<<<dim3(4, 96), 256>>>(q, k, v, ln_g, ln_b, W_in);
    head_stats<<<(2 * NPAIR * 1024) / 8, 256>>>();
    macc<<<NPAIR * 8, 256>>>();
    mreduce<<<NPAIR, 256>>>();
    apply_k<<<NPAIR * 32, 256>>>(cov_w, var_w);
    gemm_bias<<<dim3(4, 32), 256>>>(W_out, b_out, out);
}

// round 3
// speedup vs baseline: 1.8349x; 1.8349x over previous
#include <cuda_runtime.h>
#include <cuda_bf16.h>
#include <cstdint>

// Problem constants: B=4, S=1024, D=512, H=8, DH=64
#define RQ   4096
#define R3   12288
#define DD   512
#define NPAIR 32
#define SPLITS 16
#define LN_EPS 1e-5f

// ---------------- scratch ----------------
__device__ float         g_f[3 * RQ * DD];        // fp32 f_q|f_k|f_v
__device__ __nv_bfloat16 g_Ahi[R3 * DD];
__device__ __nv_bfloat16 g_Alo[R3 * DD];
__device__ __nv_bfloat16 g_Bhi[2 * DD * DD];      // W_in^T | W_out^T (hi)
__device__ __nv_bfloat16 g_Blo[2 * DD * DD];
__device__ __nv_bfloat16 g_ghi[RQ * DD];
__device__ __nv_bfloat16 g_glo[RQ * DD];
__device__ float g_hmu[2 * NPAIR * 1024];
__device__ float g_hinvn[2 * NPAIR * 1024];
__device__ float g_hvar[2 * NPAIR * 1024];
__device__ float g_Mpart[NPAIR * SPLITS * 2 * 4096];
__device__ float g_rpart[NPAIR * SPLITS * 64];
__device__ float g_M[NPAIR * 2 * 4096];
__device__ float g_r[NPAIR * 64];

// ---------------- helpers ----------------
__device__ __forceinline__ uint32_t smem_u32(const void* p) {
    uint32_t a;
    asm("{ .reg .u64 t; cvta.to.shared.u64 t, %1; cvt.u32.u64 %0, t; }" : "=r"(a) : "l"(p));
    return a;
}
__device__ __forceinline__ void cp16(uint32_t dst, const void* src) {
    asm volatile("cp.async.cg.shared.global [%0], [%1], 16;" :: "r"(dst), "l"(src));
}
__device__ __forceinline__ void cp_commit() {
    asm volatile("cp.async.commit_group;");
}
__device__ __forceinline__ void ldsm4(uint32_t& r0, uint32_t& r1, uint32_t& r2, uint32_t& r3,
                                      uint32_t addr) {
    asm volatile("ldmatrix.sync.aligned.m8n8.x4.shared.b16 {%0,%1,%2,%3}, [%4];"
                 : "=r"(r0), "=r"(r1), "=r"(r2), "=r"(r3) : "r"(addr));
}
__device__ __forceinline__ void mma16816(float& c0, float& c1, float& c2, float& c3,
                                         uint32_t a0, uint32_t a1, uint32_t a2, uint32_t a3,
                                         uint32_t b0, uint32_t b1) {
    asm volatile(
        "mma.sync.aligned.m16n8k16.row.col.f32.bf16.bf16.f32 "
        "{%0,%1,%2,%3}, {%4,%5,%6,%7}, {%8,%9}, {%0,%1,%2,%3};"
        : "+f"(c0), "+f"(c1), "+f"(c2), "+f"(c3)
        : "r"(a0), "r"(a1), "r"(a2), "r"(a3), "r"(b0), "r"(b1));
}

// ---------------- 1) LN + bf16 hi/lo split ----------------
__global__ void __launch_bounds__(256) ln_convert(
    const float* __restrict__ q, const float* __restrict__ k,
    const float* __restrict__ v, const float* __restrict__ lng,
    const float* __restrict__ lnb)
{
    int gw   = blockIdx.x * 8 + (threadIdx.x >> 5);
    int lane = threadIdx.x & 31;
    const float* src = (gw < RQ) ? q : (gw < 2 * RQ ? k : v);
    int row = gw & (RQ - 1);
    const float4* p = (const float4*)(src + (size_t)row * DD);
    float4 x[4];
    float s = 0.f, ss = 0.f;
#pragma unroll
    for (int i = 0; i < 4; i++) {
        x[i] = p[lane + i * 32];
        s  += x[i].x + x[i].y + x[i].z + x[i].w;
        ss += x[i].x * x[i].x + x[i].y * x[i].y + x[i].z * x[i].z + x[i].w * x[i].w;
    }
#pragma unroll
    for (int o = 16; o; o >>= 1) {
        s  += __shfl_xor_sync(0xffffffffu, s, o);
        ss += __shfl_xor_sync(0xffffffffu, ss, o);
    }
    float mu = s * (1.f / 512.f);
    float rs = rsqrtf(ss * (1.f / 512.f) - mu * mu + LN_EPS);
#pragma unroll
    for (int i = 0; i < 4; i++) {
        float4 gg = ((const float4*)lng)[lane + i * 32];
        float4 bb = ((const float4*)lnb)[lane + i * 32];
        float y0 = (x[i].x - mu) * rs * gg.x + bb.x;
        float y1 = (x[i].y - mu) * rs * gg.y + bb.y;
        float y2 = (x[i].z - mu) * rs * gg.z + bb.z;
        float y3 = (x[i].w - mu) * rs * gg.w + bb.w;
        __nv_bfloat162 h01 = __floats2bfloat162_rn(y0, y1);
        __nv_bfloat162 h23 = __floats2bfloat162_rn(y2, y3);
        __nv_bfloat162 l01 = __floats2bfloat162_rn(y0 - __bfloat162float(h01.x),
                                                   y1 - __bfloat162float(h01.y));
        __nv_bfloat162 l23 = __floats2bfloat162_rn(y2 - __bfloat162float(h23.x),
                                                   y3 - __bfloat162float(h23.y));
        size_t off = (size_t)gw * DD + 4 * (lane + 32 * i);
        uint2 hv, lv;
        hv.x = *(uint32_t*)&h01; hv.y = *(uint32_t*)&h23;
        lv.x = *(uint32_t*)&l01; lv.y = *(uint32_t*)&l23;
        *(uint2*)&g_Ahi[off] = hv;
        *(uint2*)&g_Alo[off] = lv;
    }
}

// ---------------- 2) transpose + split weights ----------------
__global__ void __launch_bounds__(256) convert_W(const float* __restrict__ Win,
                                                 const float* __restrict__ Wout)
{
    __shared__ float ts[32][33];
    const float* W = blockIdx.z ? Wout : Win;
    size_t base = (size_t)blockIdx.z * DD * DD;
    int k0 = blockIdx.x * 32, n0 = blockIdx.y * 32;
    int tx = threadIdx.x & 31, ty = threadIdx.x >> 5;
#pragma unroll
    for (int i = 0; i < 4; i++)
        ts[ty + 8 * i][tx] = W[(size_t)(k0 + ty + 8 * i) * DD + n0 + tx];
    __syncthreads();
#pragma unroll
    for (int i = 0; i < 4; i++) {
        int n = n0 + ty + 8 * i, kk = k0 + tx;
        float val = ts[tx][ty + 8 * i];
        __nv_bfloat16 h = __float2bfloat16_rn(val);
        __nv_bfloat16 l = __float2bfloat16_rn(val - __bfloat162float(h));
        g_Bhi[base + (size_t)n * DD + kk] = h;
        g_Blo[base + (size_t)n * DD + kk] = l;
    }
}

// ---------------- 3) HMMA GEMM, bf16x3: C[M,512] = A @ B^T ----------------
// CTA tile 128x128, K-chunk 32, double-buffered cp.async, 8 warps (64x32 each).
#define RS 40                      // smem row stride (bf16)
#define TILE_B (128 * RS * 2)      // 10240 bytes per operand tile
#define BUF_B  (4 * TILE_B)        // Ahi|Alo|Bhi|Blo per buffer
#define GEMM_SMEM (2 * BUF_B)      // 81920 bytes

__global__ void __launch_bounds__(256, 1) gemm_bf3(
    const __nv_bfloat16* __restrict__ Ahi, const __nv_bfloat16* __restrict__ Alo,
    const __nv_bfloat16* __restrict__ Bhi, const __nv_bfloat16* __restrict__ Blo,
    float* __restrict__ C, const float* __restrict__ bias, int mode)
{
    extern __shared__ char smem[];
    uint32_t sb = smem_u32(smem);
    int t = threadIdx.x, wid = t >> 5, lane = t & 31;
    int n0 = blockIdx.x * 128, m0 = blockIdx.y * 128;
    int wm = wid >> 2, wn = wid & 3;

    float acc[4][4][4];
#pragma unroll
    for (int i = 0; i < 4; i++)
#pragma unroll
        for (int j = 0; j < 4; j++)
#pragma unroll
            for (int r = 0; r < 4; r++) acc[i][j][r] = 0.f;

    // per-thread load coords: 2 units/operand, unit u -> row u>>2, seg u&3 (8 bf16)
    int r0l = t >> 2, seg = t & 3;

    auto issue = [&](int c, int buf) {
        int k0 = c * 32;
        uint32_t d0 = sb + buf * BUF_B;
#pragma unroll
        for (int i = 0; i < 2; i++) {
            int row = r0l + i * 64;
            uint32_t doff = (row * RS + seg * 8) * 2;
            size_t ga = (size_t)(m0 + row) * DD + k0 + seg * 8;
            size_t gb = (size_t)(n0 + row) * DD + k0 + seg * 8;
            cp16(d0 + doff,              Ahi + ga);
            cp16(d0 + TILE_B + doff,     Alo + ga);
            cp16(d0 + 2 * TILE_B + doff, Bhi + gb);
            cp16(d0 + 3 * TILE_B + doff, Blo + gb);
        }
        cp_commit();
    };

    issue(0, 0);
    int g = lane >> 3, rl = lane & 7;

    for (int c = 0; c < 16; c++) {
        int buf = c & 1;
        if (c < 15) issue(c + 1, buf ^ 1);
        if (c < 15) asm volatile("cp.async.wait_group 1;");
        else        asm volatile("cp.async.wait_group 0;");
        __syncthreads();

        uint32_t aBase = sb + buf * BUF_B;
        uint32_t bBase = aBase + 2 * TILE_B;
#pragma unroll
        for (int h = 0; h < 2; h++) {
            // A fragments: 4 m16 tiles, hi & lo
            uint32_t aH[4][4], aL[4][4];
#pragma unroll
            for (int it = 0; it < 4; it++) {
                int row = wm * 64 + it * 16 + rl + (g & 1) * 8;
                int kc  = h * 16 + (g & 2) * 4;
                uint32_t ad = aBase + (row * RS + kc) * 2;
                ldsm4(aH[it][0], aH[it][1], aH[it][2], aH[it][3], ad);
                ldsm4(aL[it][0], aL[it][1], aL[it][2], aL[it][3], ad + TILE_B);
            }
            // B fragments: 4 n8 tiles (2 ldsm4 each for hi/lo)
            uint32_t bH[4][2], bL[4][2];
#pragma unroll
            for (int jp = 0; jp < 2; jp++) {
                int row = wn * 32 + jp * 16 + rl + (g >> 1) * 8;
                int kc  = h * 16 + (g & 1) * 8;
                uint32_t bd = bBase + (row * RS + kc) * 2;
                ldsm4(bH[2 * jp][0], bH[2 * jp][1], bH[2 * jp + 1][0], bH[2 * jp + 1][1], bd);
                ldsm4(bL[2 * jp][0], bL[2 * jp][1], bL[2 * jp + 1][0], bL[2 * jp + 1][1],
                      bd + TILE_B);
            }
#pragma unroll
            for (int it = 0; it < 4; it++)
#pragma unroll
                for (int jt = 0; jt < 4; jt++) {
                    mma16816(acc[it][jt][0], acc[it][jt][1], acc[it][jt][2], acc[it][jt][3],
                             aH[it][0], aH[it][1], aH[it][2], aH[it][3],
                             bH[jt][0], bH[jt][1]);
                    mma16816(acc[it][jt][0], acc[it][jt][1], acc[it][jt][2], acc[it][jt][3],
                             aH[it][0], aH[it][1], aH[it][2], aH[it][3],
                             bL[jt][0], bL[jt][1]);
                    mma16816(acc[it][jt][0], acc[it][jt][1], acc[it][jt][2], acc[it][jt][3],
                             aL[it][0], aL[it][1], aL[it][2], aL[it][3],
                             bH[jt][0], bH[jt][1]);
                }
        }
        __syncthreads();
    }

    // epilogue
    int rr = lane >> 2, cc = 2 * (lane & 3);
#pragma unroll
    for (int it = 0; it < 4; it++) {
        int row = m0 + wm * 64 + it * 16 + rr;
#pragma unroll
        for (int jt = 0; jt < 4; jt++) {
            int col = n0 + wn * 32 + jt * 8 + cc;
            if (mode == 0) {
                *(float2*)&C[(size_t)row * DD + col] =
                    make_float2(acc[it][jt][0], acc[it][jt][1]);
                *(float2*)&C[(size_t)(row + 8) * DD + col] =
                    make_float2(acc[it][jt][2], acc[it][jt][3]);
            } else {
                float2 bb = *(const float2*)&bias[col];
                *(float2*)&C[(size_t)row * DD + col] =
                    make_float2(acc[it][jt][0] + bb.x, acc[it][jt][1] + bb.y);
                *(float2*)&C[(size_t)(row + 8) * DD + col] =
                    make_float2(acc[it][jt][2] + bb.x, acc[it][jt][3] + bb.y);
            }
        }
    }
}

// ---------------- 4) per-head row stats for f_q, f_k ----------------
__global__ void head_stats()
{
    int gw   = (blockIdx.x * blockDim.x + threadIdx.x) >> 5;
    int lane = threadIdx.x & 31;
    if (gw >= 2 * NPAIR * 1024) return;
    int which = gw >> 15;
    int rem   = gw & 32767;
    int hb    = rem >> 10;
    int m     = rem & 1023;
    int h = hb >> 2, b = hb & 3;
    const float* p = g_f + (size_t)which * RQ * DD + (size_t)(b * 1024 + m) * DD + h * 64;
    float x0 = p[lane], x1 = p[lane + 32];
    float s = x0 + x1, ss = x0 * x0 + x1 * x1;
#pragma unroll
    for (int o = 16; o; o >>= 1) {
        s  += __shfl_xor_sync(0xffffffffu, s, o);
        ss += __shfl_xor_sync(0xffffffffu, ss, o);
    }
    if (lane == 0) {
        g_hmu[gw]   = s * (1.f / 64.f);
        g_hinvn[gw] = rsqrtf(ss);
        g_hvar[gw]  = (ss - s * s * (1.f / 64.f)) * (1.f / 63.f);
    }
}

// ---------------- 5) M1/M2/r partial accumulation ----------------
__global__ void __launch_bounds__(256) macc()
{
    __shared__ float Ks[32][64];
    __shared__ float Vs[32][64];
    __shared__ float skm[32], sikn[32], skv[32];
    int t = threadIdx.x;
    int pair  = blockIdx.x >> 4;
    int split = blockIdx.x & 15;
    int h = pair >> 2, b = pair & 3;
    const float* fk = g_f + (size_t)RQ * DD     + (size_t)(b * 1024) * DD + h * 64;
    const float* fv = g_f + (size_t)2 * RQ * DD + (size_t)(b * 1024) * DD + h * 64;
    int tx = t & 15, ty = t >> 4;
    int d0 = ty * 4, e0 = tx * 4;
    float M1a[4][4] = {}, M2a[4][4] = {}, ra[4] = {};
    int mbase0 = split * 64;

    for (int c = 0; c < 2; c++) {
        int mbase = mbase0 + c * 32;
#pragma unroll
        for (int i = 0; i < 2; i++) {
            int fi = t + i * 256;
            int rr = fi >> 4;
            int c4 = (fi & 15) * 4;
            *(float4*)&Ks[rr][c4] = *(const float4*)(fk + (size_t)(mbase + rr) * DD + c4);
            *(float4*)&Vs[rr][c4] = *(const float4*)(fv + (size_t)(mbase + rr) * DD + c4);
        }
        if (t < 32) {
            int idx = 32768 + pair * 1024 + mbase + t;
            skm[t]  = g_hmu[idx];
            sikn[t] = g_hinvn[idx];
            skv[t]  = g_hvar[idx];
        }
        __syncthreads();
#pragma unroll 8
        for (int mm = 0; mm < 32; mm++) {
            float km = skm[mm], ikn = sikn[mm];
            float4 kk4 = *(float4*)&Ks[mm][d0];
            float4 vv4 = *(float4*)&Vs[mm][e0];
            float a1[4] = {kk4.x - km, kk4.y - km, kk4.z - km, kk4.w - km};
            float a2[4] = {kk4.x * ikn, kk4.y * ikn, kk4.z * ikn, kk4.w * ikn};
            float vv[4] = {vv4.x, vv4.y, vv4.z, vv4.w};
#pragma unroll
            for (int i = 0; i < 4; i++)
#pragma unroll
                for (int j = 0; j < 4; j++) {
                    M1a[i][j] += a1[i] * vv[j];
                    M2a[i][j] += a2[i] * vv[j];
                }
        }
        if (ty == 0) {
#pragma unroll 8
            for (int mm = 0; mm < 32; mm++) {
                float kvv = skv[mm];
#pragma unroll
                for (int j = 0; j < 4; j++) ra[j] += kvv * Vs[mm][e0 + j];
            }
        }
        __syncthreads();
    }
    float* mp = g_Mpart + (size_t)blockIdx.x * 8192;
#pragma unroll
    for (int i = 0; i < 4; i++)
#pragma unroll
        for (int j = 0; j < 4; j++) {
            mp[(d0 + i) * 64 + e0 + j]        = M1a[i][j];
            mp[4096 + (d0 + i) * 64 + e0 + j] = M2a[i][j];
        }
    if (ty == 0)
#pragma unroll
        for (int j = 0; j < 4; j++) g_rpart[blockIdx.x * 64 + e0 + j] = ra[j];
}

// ---------------- 6) reduce partials ----------------
__global__ void mreduce()
{
    int p = blockIdx.x, t = threadIdx.x;
    for (int idx = t; idx < 8192; idx += 256) {
        float s = 0.f;
#pragma unroll
        for (int sp = 0; sp < SPLITS; sp++)
            s += g_Mpart[(size_t)(p * SPLITS + sp) * 8192 + idx];
        g_M[(size_t)p * 8192 + idx] = s;
    }
    if (t < 64) {
        float s = 0.f;
#pragma unroll
        for (int sp = 0; sp < SPLITS; sp++) s += g_rpart[(p * SPLITS + sp) * 64 + t];
        g_r[p * 64 + t] = s;
    }
}

// ---------------- 7) apply, emits bf16 hi/lo ----------------
__global__ void __launch_bounds__(256) apply_k(const float* __restrict__ cov_w,
                                               const float* __restrict__ var_w)
{
    __shared__ float Ms[2 * 4096];
    __shared__ float qs[64][34];
    __shared__ float scs1[64], srs[64];
    __shared__ float sbeta[32], sgamma[32], smual[32];
    int t = threadIdx.x;
    int pair  = blockIdx.x >> 5;
    int ntile = blockIdx.x & 31;
    int h = pair >> 2, b = pair & 3;
    float cw = cov_w[0], vw = var_w[0];
    float w3 = 1.f - cw - vw;
    float alpha = cw * (1.f / 64.f);

    const float* msrc = g_M + (size_t)pair * 8192;
#pragma unroll
    for (int i = 0; i < 8; i++) {
        int fi = t + i * 256;
        ((float4*)Ms)[fi] = ((const float4*)msrc)[fi];
    }
    int n0 = ntile * 32;
    const float* fq = g_f + (size_t)(b * 1024 + n0) * DD + h * 64;
#pragma unroll
    for (int i = 0; i < 2; i++) {
        int fi = t + i * 256;
        int rr = fi >> 4, c4 = (fi & 15) * 4;
        float4 x = *(const float4*)(fq + (size_t)rr * DD + c4);
        qs[c4 + 0][rr] = x.x; qs[c4 + 1][rr] = x.y;
        qs[c4 + 2][rr] = x.z; qs[c4 + 3][rr] = x.w;
    }
    if (t < 32) {
        int idx = pair * 1024 + n0 + t;
        float mu = g_hmu[idx], invn = g_hinvn[idx], var = g_hvar[idx];
        sbeta[t]  = w3 * invn;
        sgamma[t] = vw * (1.f / 64.f) * var;
        smual[t]  = alpha * mu;
    }
    if (t < 64) srs[t] = g_r[pair * 64 + t];
    __syncthreads();
    if (t < 64) {
        float s = 0.f;
#pragma unroll
        for (int d = 0; d < 64; d++) s += Ms[d * 64 + t];
        scs1[t] = s;
    }
    __syncthreads();

    int tx = t & 15, ty = t >> 4;
    int e0 = tx * 4, r0 = ty * 2;
    float t1[2][4] = {}, t2[2][4] = {};
#pragma unroll 8
    for (int d = 0; d < 64; d++) {
        float4 m1 = *(float4*)&Ms[d * 64 + e0];
        float4 m2 = *(float4*)&Ms[4096 + d * 64 + e0];
        float q0 = qs[d][r0], q1 = qs[d][r0 + 1];
        t1[0][0] += q0 * m1.x; t1[0][1] += q0 * m1.y; t1[0][2] += q0 * m1.z; t1[0][3] += q0 * m1.w;
        t1[1][0] += q1 * m1.x; t1[1][1] += q1 * m1.y; t1[1][2] += q1 * m1.z; t1[1][3] += q1 * m1.w;
        t2[0][0] += q0 * m2.x; t2[0][1] += q0 * m2.y; t2[0][2] += q0 * m2.z; t2[0][3] += q0 * m2.w;
        t2[1][0] += q1 * m2.x; t2[1][1] += q1 * m2.y; t2[1][2] += q1 * m2.z; t2[1][3] += q1 * m2.w;
    }
#pragma unroll
    for (int i = 0; i < 2; i++) {
        int row = r0 + i;
        int n = n0 + row;
        float beta = sbeta[row], gamma = sgamma[row], mal = smual[row];
        float o0 = alpha * t1[i][0] - mal * scs1[e0 + 0] + beta * t2[i][0] + gamma * srs[e0 + 0];
        float o1 = alpha * t1[i][1] - mal * scs1[e0 + 1] + beta * t2[i][1] + gamma * srs[e0 + 1];
        float o2 = alpha * t1[i][2] - mal * scs1[e0 + 2] + beta * t2[i][2] + gamma * srs[e0 + 2];
        float o3 = alpha * t1[i][3] - mal * scs1[e0 + 3] + beta * t2[i][3] + gamma * srs[e0 + 3];
        __nv_bfloat162 h01 = __floats2bfloat162_rn(o0, o1);
        __nv_bfloat162 h23 = __floats2bfloat162_rn(o2, o3);
        __nv_bfloat162 l01 = __floats2bfloat162_rn(o0 - __bfloat162float(h01.x),
                                                   o1 - __bfloat162float(h01.y));
        __nv_bfloat162 l23 = __floats2bfloat162_rn(o2 - __bfloat162float(h23.x),
                                                   o3 - __bfloat162float(h23.y));
        size_t off = (size_t)(b * 1024 + n) * DD + h * 64 + e0;
        uint2 hv, lv;
        hv.x = *(uint32_t*)&h01; hv.y = *(uint32_t*)&h23;
        lv.x = *(uint32_t*)&l01; lv.y = *(uint32_t*)&l23;
        *(uint2*)&g_ghi[off] = hv;
        *(uint2*)&g_glo[off] = lv;
    }
}

// ---------------- launch ----------------
extern "C" void kernel_launch(void* const* d_in, const int* in_sizes, int n_in,
                              void* d_out, int out_size)
{
    const float* q     = (const float*)d_in[0];
    const float* k     = (const float*)d_in[1];
    const float* v     = (const float*)d_in[2];
    const float* ln_g  = (const float*)d_in[3];
    const float* ln_b  = (const float*)d_in[4];
    const float* W_in  = (const float*)d_in[5];
    const float* W_out = (const float*)d_in[6];
    const float* b_out = (const float*)d_in[7];
    const float* cov_w = (const float*)d_in[8];
    const float* var_w = (const float*)d_in[9];
    float* out = (float*)d_out;

    cudaFuncSetAttribute(gemm_bf3, cudaFuncAttributeMaxDynamicSharedMemorySize, GEMM_SMEM);

    __nv_bfloat16 *Ahi, *Alo, *Bhi, *Blo, *ghi, *glo;
    float* f;
    cudaGetSymbolAddress((void**)&Ahi, g_Ahi);
    cudaGetSymbolAddress((void**)&Alo, g_Alo);
    cudaGetSymbolAddress((void**)&Bhi, g_Bhi);
    cudaGetSymbolAddress((void**)&Blo, g_Blo);
    cudaGetSymbolAddress((void**)&ghi, g_ghi);
    cudaGetSymbolAddress((void**)&glo, g_glo);
    cudaGetSymbolAddress((void**)&f,   g_f);

    ln_convert<<<R3 / 8, 256>>>(q, k, v, ln_g, ln_b);
    convert_W<<<dim3(16, 16, 2), 256>>>(W_in, W_out);
    gemm_bf3<<<dim3(4, 96), 256, GEMM_SMEM>>>(Ahi, Alo, Bhi, Blo, f, nullptr, 0);
    head_stats<<<(2 * NPAIR * 1024) / 8, 256>>>();
    macc<<<NPAIR * SPLITS, 256>>>();
    mreduce<<<NPAIR, 256>>>();
    apply_k<<<NPAIR * 32, 256>>>(cov_w, var_w);
    gemm_bf3<<<dim3(4, 32), 256, GEMM_SMEM>>>(ghi, glo, Bhi + DD * DD, Blo + DD * DD,
                                              out, b_out, 1);
}

// round 4
// speedup vs baseline: 1.9438x; 1.0594x over previous
#include <cuda_runtime.h>
#include <cuda_bf16.h>
#include <cstdint>

// Problem constants: B=4, S=1024, D=512, H=8, DH=64
#define RQ   4096
#define R3   12288
#define DD   512
#define NPAIR 32
#define SPLITS 16
#define LN_EPS 1e-5f

// ---------------- scratch ----------------
__device__ float         g_f[3 * RQ * DD];        // fp32 f_q|f_k|f_v
__device__ __nv_bfloat16 g_Ahi[R3 * DD];
__device__ __nv_bfloat16 g_Alo[R3 * DD];
__device__ __nv_bfloat16 g_Bhi[2 * DD * DD];      // W_in^T | W_out^T (hi)
__device__ __nv_bfloat16 g_Blo[2 * DD * DD];
__device__ __nv_bfloat16 g_ghi[RQ * DD];
__device__ __nv_bfloat16 g_glo[RQ * DD];
__device__ float g_hmu[2 * NPAIR * 1024];
__device__ float g_hinvn[2 * NPAIR * 1024];
__device__ float g_hvar[2 * NPAIR * 1024];
__device__ float g_Mpart[NPAIR * SPLITS * 2 * 4096];
__device__ float g_rpart[NPAIR * SPLITS * 64];
__device__ float g_M[NPAIR * 2 * 4096];
__device__ float g_r[NPAIR * 64];

// ---------------- helpers ----------------
__device__ __forceinline__ uint32_t smem_u32(const void* p) {
    uint32_t a;
    asm("{ .reg .u64 t; cvta.to.shared.u64 t, %1; cvt.u32.u64 %0, t; }" : "=r"(a) : "l"(p));
    return a;
}
__device__ __forceinline__ void cp16(uint32_t dst, const void* src) {
    asm volatile("cp.async.cg.shared.global [%0], [%1], 16;" :: "r"(dst), "l"(src));
}
__device__ __forceinline__ void cp_commit() {
    asm volatile("cp.async.commit_group;");
}
__device__ __forceinline__ void ldsm4(uint32_t& r0, uint32_t& r1, uint32_t& r2, uint32_t& r3,
                                      uint32_t addr) {
    asm volatile("ldmatrix.sync.aligned.m8n8.x4.shared.b16 {%0,%1,%2,%3}, [%4];"
                 : "=r"(r0), "=r"(r1), "=r"(r2), "=r"(r3) : "r"(addr));
}
__device__ __forceinline__ void mma16816(float& c0, float& c1, float& c2, float& c3,
                                         uint32_t a0, uint32_t a1, uint32_t a2, uint32_t a3,
                                         uint32_t b0, uint32_t b1) {
    asm volatile(
        "mma.sync.aligned.m16n8k16.row.col.f32.bf16.bf16.f32 "
        "{%0,%1,%2,%3}, {%4,%5,%6,%7}, {%8,%9}, {%0,%1,%2,%3};"
        : "+f"(c0), "+f"(c1), "+f"(c2), "+f"(c3)
        : "r"(a0), "r"(a1), "r"(a2), "r"(a3), "r"(b0), "r"(b1));
}

// ---------------- 1) LN + bf16 hi/lo split ----------------
__global__ void __launch_bounds__(256) ln_convert(
    const float* __restrict__ q, const float* __restrict__ k,
    const float* __restrict__ v, const float* __restrict__ lng,
    const float* __restrict__ lnb)
{
    int gw   = blockIdx.x * 8 + (threadIdx.x >> 5);
    int lane = threadIdx.x & 31;
    const float* src = (gw < RQ) ? q : (gw < 2 * RQ ? k : v);
    int row = gw & (RQ - 1);
    const float4* p = (const float4*)(src + (size_t)row * DD);
    float4 x[4];
    float s = 0.f, ss = 0.f;
#pragma unroll
    for (int i = 0; i < 4; i++) {
        x[i] = p[lane + i * 32];
        s  += x[i].x + x[i].y + x[i].z + x[i].w;
        ss += x[i].x * x[i].x + x[i].y * x[i].y + x[i].z * x[i].z + x[i].w * x[i].w;
    }
#pragma unroll
    for (int o = 16; o; o >>= 1) {
        s  += __shfl_xor_sync(0xffffffffu, s, o);
        ss += __shfl_xor_sync(0xffffffffu, ss, o);
    }
    float mu = s * (1.f / 512.f);
    float rs = rsqrtf(ss * (1.f / 512.f) - mu * mu + LN_EPS);
#pragma unroll
    for (int i = 0; i < 4; i++) {
        float4 gg = ((const float4*)lng)[lane + i * 32];
        float4 bb = ((const float4*)lnb)[lane + i * 32];
        float y0 = (x[i].x - mu) * rs * gg.x + bb.x;
        float y1 = (x[i].y - mu) * rs * gg.y + bb.y;
        float y2 = (x[i].z - mu) * rs * gg.z + bb.z;
        float y3 = (x[i].w - mu) * rs * gg.w + bb.w;
        __nv_bfloat162 h01 = __floats2bfloat162_rn(y0, y1);
        __nv_bfloat162 h23 = __floats2bfloat162_rn(y2, y3);
        __nv_bfloat162 l01 = __floats2bfloat162_rn(y0 - __bfloat162float(h01.x),
                                                   y1 - __bfloat162float(h01.y));
        __nv_bfloat162 l23 = __floats2bfloat162_rn(y2 - __bfloat162float(h23.x),
                                                   y3 - __bfloat162float(h23.y));
        size_t off = (size_t)gw * DD + 4 * (lane + 32 * i);
        uint2 hv, lv;
        hv.x = *(uint32_t*)&h01; hv.y = *(uint32_t*)&h23;
        lv.x = *(uint32_t*)&l01; lv.y = *(uint32_t*)&l23;
        *(uint2*)&g_Ahi[off] = hv;
        *(uint2*)&g_Alo[off] = lv;
    }
}

// ---------------- 2) transpose + split weights ----------------
__global__ void __launch_bounds__(256) convert_W(const float* __restrict__ Win,
                                                 const float* __restrict__ Wout)
{
    __shared__ float ts[32][33];
    const float* W = blockIdx.z ? Wout : Win;
    size_t base = (size_t)blockIdx.z * DD * DD;
    int k0 = blockIdx.x * 32, n0 = blockIdx.y * 32;
    int tx = threadIdx.x & 31, ty = threadIdx.x >> 5;
#pragma unroll
    for (int i = 0; i < 4; i++)
        ts[ty + 8 * i][tx] = W[(size_t)(k0 + ty + 8 * i) * DD + n0 + tx];
    __syncthreads();
#pragma unroll
    for (int i = 0; i < 4; i++) {
        int n = n0 + ty + 8 * i, kk = k0 + tx;
        float val = ts[tx][ty + 8 * i];
        __nv_bfloat16 h = __float2bfloat16_rn(val);
        __nv_bfloat16 l = __float2bfloat16_rn(val - __bfloat162float(h));
        g_Bhi[base + (size_t)n * DD + kk] = h;
        g_Blo[base + (size_t)n * DD + kk] = l;
    }
}

// ---------------- 3) HMMA GEMM, bf16x3: C[M,512] = A @ B^T ----------------
// CTA tile 128x128, K-chunk 32, double-buffered cp.async, 8 warps (64x32 each).
// mode 0: also emit per-head (64-col) row stats fused in the epilogue.
#define RS 40                      // smem row stride (bf16)
#define TILE_B (128 * RS * 2)      // 10240 bytes per operand tile
#define BUF_B  (4 * TILE_B)        // Ahi|Alo|Bhi|Blo per buffer
#define GEMM_SMEM (2 * BUF_B)      // 81920 bytes

__global__ void __launch_bounds__(256, 2) gemm_bf3(
    const __nv_bfloat16* __restrict__ Ahi, const __nv_bfloat16* __restrict__ Alo,
    const __nv_bfloat16* __restrict__ Bhi, const __nv_bfloat16* __restrict__ Blo,
    float* __restrict__ C, const float* __restrict__ bias, int mode)
{
    extern __shared__ char smem[];
    uint32_t sb = smem_u32(smem);
    int t = threadIdx.x, wid = t >> 5, lane = t & 31;
    int n0 = blockIdx.x * 128, m0 = blockIdx.y * 128;
    int wm = wid >> 2, wn = wid & 3;

    float acc[4][4][4];
#pragma unroll
    for (int i = 0; i < 4; i++)
#pragma unroll
        for (int j = 0; j < 4; j++)
#pragma unroll
            for (int r = 0; r < 4; r++) acc[i][j][r] = 0.f;

    int r0l = t >> 2, seg = t & 3;

    auto issue = [&](int c, int buf) {
        int k0 = c * 32;
        uint32_t d0 = sb + buf * BUF_B;
#pragma unroll
        for (int i = 0; i < 2; i++) {
            int row = r0l + i * 64;
            uint32_t doff = (row * RS + seg * 8) * 2;
            size_t ga = (size_t)(m0 + row) * DD + k0 + seg * 8;
            size_t gb = (size_t)(n0 + row) * DD + k0 + seg * 8;
            cp16(d0 + doff,              Ahi + ga);
            cp16(d0 + TILE_B + doff,     Alo + ga);
            cp16(d0 + 2 * TILE_B + doff, Bhi + gb);
            cp16(d0 + 3 * TILE_B + doff, Blo + gb);
        }
        cp_commit();
    };

    issue(0, 0);
    int g = lane >> 3, rl = lane & 7;

    for (int c = 0; c < 16; c++) {
        int buf = c & 1;
        if (c < 15) issue(c + 1, buf ^ 1);
        if (c < 15) asm volatile("cp.async.wait_group 1;");
        else        asm volatile("cp.async.wait_group 0;");
        __syncthreads();

        uint32_t aBase = sb + buf * BUF_B;
        uint32_t bBase = aBase + 2 * TILE_B;
#pragma unroll
        for (int h = 0; h < 2; h++) {
            uint32_t aH[4][4], aL[4][4];
#pragma unroll
            for (int it = 0; it < 4; it++) {
                int row = wm * 64 + it * 16 + rl + (g & 1) * 8;
                int kc  = h * 16 + (g & 2) * 4;
                uint32_t ad = aBase + (row * RS + kc) * 2;
                ldsm4(aH[it][0], aH[it][1], aH[it][2], aH[it][3], ad);
                ldsm4(aL[it][0], aL[it][1], aL[it][2], aL[it][3], ad + TILE_B);
            }
            uint32_t bH[4][2], bL[4][2];
#pragma unroll
            for (int jp = 0; jp < 2; jp++) {
                int row = wn * 32 + jp * 16 + rl + (g >> 1) * 8;
                int kc  = h * 16 + (g & 1) * 8;
                uint32_t bd = bBase + (row * RS + kc) * 2;
                ldsm4(bH[2 * jp][0], bH[2 * jp][1], bH[2 * jp + 1][0], bH[2 * jp + 1][1], bd);
                ldsm4(bL[2 * jp][0], bL[2 * jp][1], bL[2 * jp + 1][0], bL[2 * jp + 1][1],
                      bd + TILE_B);
            }
#pragma unroll
            for (int it = 0; it < 4; it++)
#pragma unroll
                for (int jt = 0; jt < 4; jt++) {
                    mma16816(acc[it][jt][0], acc[it][jt][1], acc[it][jt][2], acc[it][jt][3],
                             aH[it][0], aH[it][1], aH[it][2], aH[it][3],
                             bH[jt][0], bH[jt][1]);
                    mma16816(acc[it][jt][0], acc[it][jt][1], acc[it][jt][2], acc[it][jt][3],
                             aH[it][0], aH[it][1], aH[it][2], aH[it][3],
                             bL[jt][0], bL[jt][1]);
                    mma16816(acc[it][jt][0], acc[it][jt][1], acc[it][jt][2], acc[it][jt][3],
                             aL[it][0], aL[it][1], aL[it][2], aL[it][3],
                             bH[jt][0], bH[jt][1]);
                }
        }
        __syncthreads();
    }

    // ---------------- epilogue ----------------
    int rr = lane >> 2, cc = 2 * (lane & 3);
#pragma unroll
    for (int it = 0; it < 4; it++) {
        int row = m0 + wm * 64 + it * 16 + rr;
#pragma unroll
        for (int jt = 0; jt < 4; jt++) {
            int col = n0 + wn * 32 + jt * 8 + cc;
            if (mode == 0) {
                *(float2*)&C[(size_t)row * DD + col] =
                    make_float2(acc[it][jt][0], acc[it][jt][1]);
                *(float2*)&C[(size_t)(row + 8) * DD + col] =
                    make_float2(acc[it][jt][2], acc[it][jt][3]);
            } else {
                float2 bb = *(const float2*)&bias[col];
                *(float2*)&C[(size_t)row * DD + col] =
                    make_float2(acc[it][jt][0] + bb.x, acc[it][jt][1] + bb.y);
                *(float2*)&C[(size_t)(row + 8) * DD + col] =
                    make_float2(acc[it][jt][2] + bb.x, acc[it][jt][3] + bb.y);
            }
        }
    }

    // fused per-head row stats (mode 0, fq/fk rows only)
    if (mode == 0 && m0 < 2 * RQ) {
        float* sred = (float*)smem;   // [wn][128 rows][2] = 4KB
#pragma unroll
        for (int it = 0; it < 4; it++) {
#pragma unroll
            for (int sub = 0; sub < 2; sub++) {
                float s = 0.f, ss = 0.f;
#pragma unroll
                for (int jt = 0; jt < 4; jt++) {
                    float v0 = acc[it][jt][2 * sub], v1 = acc[it][jt][2 * sub + 1];
                    s  += v0 + v1;
                    ss += v0 * v0 + v1 * v1;
                }
#pragma unroll
                for (int o = 1; o <= 2; o <<= 1) {
                    s  += __shfl_xor_sync(0xffffffffu, s, o);
                    ss += __shfl_xor_sync(0xffffffffu, ss, o);
                }
                if ((lane & 3) == 0) {
                    int lrow = wm * 64 + it * 16 + rr + sub * 8;
                    sred[(wn * 128 + lrow) * 2 + 0] = s;
                    sred[(wn * 128 + lrow) * 2 + 1] = ss;
                }
            }
        }
        __syncthreads();
        // 256 threads: 2 head-pairs x 128 rows
        int hp = t >> 7, lrow = t & 127;
        float s  = sred[((2 * hp) * 128 + lrow) * 2 + 0] +
                   sred[((2 * hp + 1) * 128 + lrow) * 2 + 0];
        float ss = sred[((2 * hp) * 128 + lrow) * 2 + 1] +
                   sred[((2 * hp + 1) * 128 + lrow) * 2 + 1];
        int grow = m0 + lrow;
        int tensor = grow >> 12;
        int b = (grow >> 10) & 3, m = grow & 1023;
        int h = (n0 >> 6) + hp;
        int idx = tensor * 32768 + (h * 4 + b) * 1024 + m;
        g_hmu[idx]   = s * (1.f / 64.f);
        g_hinvn[idx] = rsqrtf(ss);
        g_hvar[idx]  = (ss - s * s * (1.f / 64.f)) * (1.f / 63.f);
    }
}

// ---------------- 4) M1/M2/r partial accumulation ----------------
__global__ void __launch_bounds__(256) macc()
{
    __shared__ float Ks[32][64];
    __shared__ float Vs[32][64];
    __shared__ float skm[32], sikn[32], skv[32];
    int t = threadIdx.x;
    int pair  = blockIdx.x >> 4;
    int split = blockIdx.x & 15;
    int h = pair >> 2, b = pair & 3;
    const float* fk = g_f + (size_t)RQ * DD     + (size_t)(b * 1024) * DD + h * 64;
    const float* fv = g_f + (size_t)2 * RQ * DD + (size_t)(b * 1024) * DD + h * 64;
    int tx = t & 15, ty = t >> 4;
    int d0 = ty * 4, e0 = tx * 4;
    float M1a[4][4] = {}, M2a[4][4] = {}, ra[4] = {};
    int mbase0 = split * 64;

    for (int c = 0; c < 2; c++) {
        int mbase = mbase0 + c * 32;
#pragma unroll
        for (int i = 0; i < 2; i++) {
            int fi = t + i * 256;
            int rr = fi >> 4;
            int c4 = (fi & 15) * 4;
            *(float4*)&Ks[rr][c4] = *(const float4*)(fk + (size_t)(mbase + rr) * DD + c4);
            *(float4*)&Vs[rr][c4] = *(const float4*)(fv + (size_t)(mbase + rr) * DD + c4);
        }
        if (t < 32) {
            int idx = 32768 + pair * 1024 + mbase + t;
            skm[t]  = g_hmu[idx];
            sikn[t] = g_hinvn[idx];
            skv[t]  = g_hvar[idx];
        }
        __syncthreads();
#pragma unroll 8
        for (int mm = 0; mm < 32; mm++) {
            float km = skm[mm], ikn = sikn[mm];
            float4 kk4 = *(float4*)&Ks[mm][d0];
            float4 vv4 = *(float4*)&Vs[mm][e0];
            float a1[4] = {kk4.x - km, kk4.y - km, kk4.z - km, kk4.w - km};
            float a2[4] = {kk4.x * ikn, kk4.y * ikn, kk4.z * ikn, kk4.w * ikn};
            float vv[4] = {vv4.x, vv4.y, vv4.z, vv4.w};
#pragma unroll
            for (int i = 0; i < 4; i++)
#pragma unroll
                for (int j = 0; j < 4; j++) {
                    M1a[i][j] += a1[i] * vv[j];
                    M2a[i][j] += a2[i] * vv[j];
                }
        }
        if (ty == 0) {
#pragma unroll 8
            for (int mm = 0; mm < 32; mm++) {
                float kvv = skv[mm];
#pragma unroll
                for (int j = 0; j < 4; j++) ra[j] += kvv * Vs[mm][e0 + j];
            }
        }
        __syncthreads();
    }
    float* mp = g_Mpart + (size_t)blockIdx.x * 8192;
#pragma unroll
    for (int i = 0; i < 4; i++)
#pragma unroll
        for (int j = 0; j < 4; j++) {
            mp[(d0 + i) * 64 + e0 + j]        = M1a[i][j];
            mp[4096 + (d0 + i) * 64 + e0 + j] = M2a[i][j];
        }
    if (ty == 0)
#pragma unroll
        for (int j = 0; j < 4; j++) g_rpart[blockIdx.x * 64 + e0 + j] = ra[j];
}

// ---------------- 5) reduce partials ----------------
__global__ void mreduce()
{
    int p = blockIdx.x, t = threadIdx.x;
    for (int idx = t; idx < 8192; idx += 256) {
        float s = 0.f;
#pragma unroll
        for (int sp = 0; sp < SPLITS; sp++)
            s += g_Mpart[(size_t)(p * SPLITS + sp) * 8192 + idx];
        g_M[(size_t)p * 8192 + idx] = s;
    }
    if (t < 64) {
        float s = 0.f;
#pragma unroll
        for (int sp = 0; sp < SPLITS; sp++) s += g_rpart[(p * SPLITS + sp) * 64 + t];
        g_r[p * 64 + t] = s;
    }
}

// ---------------- 6) apply, emits bf16 hi/lo ----------------
__global__ void __launch_bounds__(256) apply_k(const float* __restrict__ cov_w,
                                               const float* __restrict__ var_w)
{
    __shared__ float Ms[2 * 4096];
    __shared__ float qs[64][34];
    __shared__ float scs1[64], srs[64];
    __shared__ float sbeta[32], sgamma[32], smual[32];
    int t = threadIdx.x;
    int pair  = blockIdx.x >> 5;
    int ntile = blockIdx.x & 31;
    int h = pair >> 2, b = pair & 3;
    float cw = cov_w[0], vw = var_w[0];
    float w3 = 1.f - cw - vw;
    float alpha = cw * (1.f / 64.f);

    const float* msrc = g_M + (size_t)pair * 8192;
#pragma unroll
    for (int i = 0; i < 8; i++) {
        int fi = t + i * 256;
        ((float4*)Ms)[fi] = ((const float4*)msrc)[fi];
    }
    int n0 = ntile * 32;
    const float* fq = g_f + (size_t)(b * 1024 + n0) * DD + h * 64;
#pragma unroll
    for (int i = 0; i < 2; i++) {
        int fi = t + i * 256;
        int rr = fi >> 4, c4 = (fi & 15) * 4;
        float4 x = *(const float4*)(fq + (size_t)rr * DD + c4);
        qs[c4 + 0][rr] = x.x; qs[c4 + 1][rr] = x.y;
        qs[c4 + 2][rr] = x.z; qs[c4 + 3][rr] = x.w;
    }
    if (t < 32) {
        int idx = pair * 1024 + n0 + t;
        float mu = g_hmu[idx], invn = g_hinvn[idx], var = g_hvar[idx];
        sbeta[t]  = w3 * invn;
        sgamma[t] = vw * (1.f / 64.f) * var;
        smual[t]  = alpha * mu;
    }
    if (t < 64) srs[t] = g_r[pair * 64 + t];
    __syncthreads();
    if (t < 64) {
        float s = 0.f;
#pragma unroll
        for (int d = 0; d < 64; d++) s += Ms[d * 64 + t];
        scs1[t] = s;
    }
    __syncthreads();

    int tx = t & 15, ty = t >> 4;
    int e0 = tx * 4, r0 = ty * 2;
    float t1[2][4] = {}, t2[2][4] = {};
#pragma unroll 8
    for (int d = 0; d < 64; d++) {
        float4 m1 = *(float4*)&Ms[d * 64 + e0];
        float4 m2 = *(float4*)&Ms[4096 + d * 64 + e0];
        float q0 = qs[d][r0], q1 = qs[d][r0 + 1];
        t1[0][0] += q0 * m1.x; t1[0][1] += q0 * m1.y; t1[0][2] += q0 * m1.z; t1[0][3] += q0 * m1.w;
        t1[1][0] += q1 * m1.x; t1[1][1] += q1 * m1.y; t1[1][2] += q1 * m1.z; t1[1][3] += q1 * m1.w;
        t2[0][0] += q0 * m2.x; t2[0][1] += q0 * m2.y; t2[0][2] += q0 * m2.z; t2[0][3] += q0 * m2.w;
        t2[1][0] += q1 * m2.x; t2[1][1] += q1 * m2.y; t2[1][2] += q1 * m2.z; t2[1][3] += q1 * m2.w;
    }
#pragma unroll
    for (int i = 0; i < 2; i++) {
        int row = r0 + i;
        int n = n0 + row;
        float beta = sbeta[row], gamma = sgamma[row], mal = smual[row];
        float o0 = alpha * t1[i][0] - mal * scs1[e0 + 0] + beta * t2[i][0] + gamma * srs[e0 + 0];
        float o1 = alpha * t1[i][1] - mal * scs1[e0 + 1] + beta * t2[i][1] + gamma * srs[e0 + 1];
        float o2 = alpha * t1[i][2] - mal * scs1[e0 + 2] + beta * t2[i][2] + gamma * srs[e0 + 2];
        float o3 = alpha * t1[i][3] - mal * scs1[e0 + 3] + beta * t2[i][3] + gamma * srs[e0 + 3];
        __nv_bfloat162 h01 = __floats2bfloat162_rn(o0, o1);
        __nv_bfloat162 h23 = __floats2bfloat162_rn(o2, o3);
        __nv_bfloat162 l01 = __floats2bfloat162_rn(o0 - __bfloat162float(h01.x),
                                                   o1 - __bfloat162float(h01.y));
        __nv_bfloat162 l23 = __floats2bfloat162_rn(o2 - __bfloat162float(h23.x),
                                                   o3 - __bfloat162float(h23.y));
        size_t off = (size_t)(b * 1024 + n) * DD + h * 64 + e0;
        uint2 hv, lv;
        hv.x = *(uint32_t*)&h01; hv.y = *(uint32_t*)&h23;
        lv.x = *(uint32_t*)&l01; lv.y = *(uint32_t*)&l23;
        *(uint2*)&g_ghi[off] = hv;
        *(uint2*)&g_glo[off] = lv;
    }
}

// ---------------- launch ----------------
extern "C" void kernel_launch(void* const* d_in, const int* in_sizes, int n_in,
                              void* d_out, int out_size)
{
    const float* q     = (const float*)d_in[0];
    const float* k     = (const float*)d_in[1];
    const float* v     = (const float*)d_in[2];
    const float* ln_g  = (const float*)d_in[3];
    const float* ln_b  = (const float*)d_in[4];
    const float* W_in  = (const float*)d_in[5];
    const float* W_out = (const float*)d_in[6];
    const float* b_out = (const float*)d_in[7];
    const float* cov_w = (const float*)d_in[8];
    const float* var_w = (const float*)d_in[9];
    float* out = (float*)d_out;

    cudaFuncSetAttribute(gemm_bf3, cudaFuncAttributeMaxDynamicSharedMemorySize, GEMM_SMEM);

    __nv_bfloat16 *Ahi, *Alo, *Bhi, *Blo, *ghi, *glo;
    float* f;
    cudaGetSymbolAddress((void**)&Ahi, g_Ahi);
    cudaGetSymbolAddress((void**)&Alo, g_Alo);
    cudaGetSymbolAddress((void**)&Bhi, g_Bhi);
    cudaGetSymbolAddress((void**)&Blo, g_Blo);
    cudaGetSymbolAddress((void**)&ghi, g_ghi);
    cudaGetSymbolAddress((void**)&glo, g_glo);
    cudaGetSymbolAddress((void**)&f,   g_f);

    ln_convert<<<R3 / 8, 256>>>(q, k, v, ln_g, ln_b);
    convert_W<<<dim3(16, 16, 2), 256>>>(W_in, W_out);
    gemm_bf3<<<dim3(4, 96), 256, GEMM_SMEM>>>(Ahi, Alo, Bhi, Blo, f, nullptr, 0);
    macc<<<NPAIR * SPLITS, 256>>>();
    mreduce<<<NPAIR, 256>>>();
    apply_k<<<NPAIR * 32, 256>>>(cov_w, var_w);
    gemm_bf3<<<dim3(4, 32), 256, GEMM_SMEM>>>(ghi, glo, Bhi + DD * DD, Blo + DD * DD,
                                              out, b_out, 1);
}